// round 8
// baseline (speedup 1.0000x reference)
#include <cuda_runtime.h>
#include <cstdint>

// Problem shape (fixed by the reference): B=4, N=M=8192, D=3, fp32.
// Exact nearest-neighbor via uniform grid binning + ring expansion.
#define BATCH   4
#define NPTS    8192
#define G       64
#define NC      (G * G * G)            // 262144 cells per grid
#define NGRIDS  (2 * BATCH)            // 8: [0..3]=y-points (per batch), [4..7]=x-points
#define TOTQ    (2 * BATCH * NPTS)     // 65536 queries
#define GS      6.4f                   // G / 10
#define H       0.15625f               // 10 / G (exact in fp32)
#define LOV     (-5.0f)

#define SCAN_CELLS      4096
#define SCANA_CTAS      (NGRIDS * NC / SCAN_CELLS)  // 512
#define BLOCKS_PER_GRID (NC / SCAN_CELLS)           // 64
#define SUMA_CTAS       64

// Static scratch (zero-initialized at load; g_cnt re-zeroed each replay).
__device__ int    g_cnt[NGRIDS * NC];      // per-cell point counts
__device__ int    g_start[NGRIDS * NC];    // per-grid exclusive CSR starts
__device__ int    g_cursor[NGRIDS * NC];   // scatter cursors
__device__ int    g_bsum[SCANA_CTAS];      // per-block totals
__device__ int    g_boff[SCANA_CTAS];      // per-grid-segmented exclusive block offsets
__device__ float4 g_pts[NGRIDS * NPTS];    // binned point copies
__device__ float  g_res[TOTQ];             // per-query min distance^2
__device__ float  g_part[SUMA_CTAS];

__device__ __forceinline__ int cellco(float v) {
    int c = (int)((v - LOV) * GS);        // arg > 0 in practice; clamp anyway
    return min(max(c, 0), G - 1);
}

// ---------------- 1. zero counts ----------------
__global__ void zero_cnt_kernel() {
    int i = blockIdx.x * blockDim.x + threadIdx.x;   // over 2M/4 int4
    ((int4*)g_cnt)[i] = make_int4(0, 0, 0, 0);
}

// ---------------- 2. count points per cell ----------------
__global__ void count_kernel(const float* __restrict__ x, const float* __restrict__ y) {
    int tid = blockIdx.x * blockDim.x + threadIdx.x;   // 65536
    int i = tid & (NPTS - 1);
    int b = (tid >> 13) & 3;
    int s = tid >> 15;                                  // 0: content y, 1: content x
    const float* src = s ? x : y;
    const float* p = src + ((size_t)b * NPTS + i) * 3;
    int cell = (cellco(p[2]) * G + cellco(p[1])) * G + cellco(p[0]);
    int g = s * BATCH + b;
    atomicAdd(&g_cnt[g * NC + cell], 1);
}

// ---------------- 3a. per-4096-cell block exclusive scan ----------------
__global__ void scanA_kernel() {
    __shared__ int sm[1024];
    int t = threadIdx.x;
    int base = blockIdx.x * SCAN_CELLS + t * 4;
    int c0 = g_cnt[base], c1 = g_cnt[base + 1], c2 = g_cnt[base + 2], c3 = g_cnt[base + 3];
    int tot = c0 + c1 + c2 + c3;
    sm[t] = tot;
    __syncthreads();
    for (int off = 1; off < 1024; off <<= 1) {
        int v = (t >= off) ? sm[t - off] : 0;
        __syncthreads();
        sm[t] += v;
        __syncthreads();
    }
    int excl = sm[t] - tot;
    g_start[base]     = excl;
    g_start[base + 1] = excl + c0;
    g_start[base + 2] = excl + c0 + c1;
    g_start[base + 3] = excl + c0 + c1 + c2;
    if (t == 1023) g_bsum[blockIdx.x] = excl + tot;
}

// ---------------- 3b. segmented (per-grid) exclusive scan of block sums ----------------
__global__ void scanB_kernel() {
    __shared__ int sm[SCANA_CTAS];
    int t = threadIdx.x;                 // 512
    int own = g_bsum[t];
    sm[t] = own;
    __syncthreads();
    for (int off = 1; off < BLOCKS_PER_GRID; off <<= 1) {
        int v = ((t & (BLOCKS_PER_GRID - 1)) >= off) ? sm[t - off] : 0;
        __syncthreads();
        sm[t] += v;
        __syncthreads();
    }
    g_boff[t] = sm[t] - own;             // exclusive within grid segment
}

// ---------------- 3c. add block offsets, init cursors ----------------
__global__ void scanC_kernel() {
    int i = blockIdx.x * blockDim.x + threadIdx.x;   // 2M
    int s = g_start[i] + g_boff[i >> 12];
    g_start[i] = s;
    g_cursor[i] = s;
}

// ---------------- 4. scatter points into CSR order ----------------
__global__ void scatter_kernel(const float* __restrict__ x, const float* __restrict__ y) {
    int tid = blockIdx.x * blockDim.x + threadIdx.x;   // 65536
    int i = tid & (NPTS - 1);
    int b = (tid >> 13) & 3;
    int s = tid >> 15;
    const float* src = s ? x : y;
    const float* p = src + ((size_t)b * NPTS + i) * 3;
    float p0 = p[0], p1 = p[1], p2 = p[2];
    int cell = (cellco(p2) * G + cellco(p1)) * G + cellco(p0);
    int g = s * BATCH + b;
    int pos = atomicAdd(&g_cursor[g * NC + cell], 1);
    g_pts[g * NPTS + pos] = make_float4(p0, p1, p2, 0.0f);
}

// ---------------- 5. query: exact NN via expanding Chebyshev rings ----------------
__device__ __forceinline__ float scan_range(const int* __restrict__ st,
                                            const int* __restrict__ cs,
                                            const float4* __restrict__ pp,
                                            int clo, int chi,
                                            float q0, float q1, float q2, float best) {
    int s0 = st[clo];
    int e0 = st[chi] + cs[chi];
    for (int j = s0; j < e0; j++) {
        float4 p = pp[j];
        float d0 = q0 - p.x, d1 = q1 - p.y, d2 = q2 - p.z;
        best = fminf(best, fmaf(d0, d0, fmaf(d1, d1, d2 * d2)));
    }
    return best;
}

__global__ void query_kernel(const float* __restrict__ x, const float* __restrict__ y) {
    int tid = blockIdx.x * blockDim.x + threadIdx.x;   // 65536
    int i = tid & (NPTS - 1);
    int b = (tid >> 13) & 3;
    int s = tid >> 15;                   // 0: x queries (search y-grid), 1: y queries
    const float* src = s ? y : x;
    const float* q = src + ((size_t)b * NPTS + i) * 3;
    float q0 = q[0], q1 = q[1], q2 = q[2];
    int g = s ? (BATCH + b) : b;         // s=0 uses y-grid (g=b); s=1 uses x-grid

    const int*    cs = g_cnt   + g * NC;
    const int*    st = g_start + g * NC;
    const float4* pp = g_pts   + g * NPTS;

    int cx = cellco(q0), cy = cellco(q1), cz = cellco(q2);
    float best = 3.0e38f;

    for (int r = 0; r < G; r++) {
        for (int dz = -r; dz <= r; dz++) {
            int z = cz + dz;
            if ((unsigned)z >= G) continue;
            bool zedge = (dz == r) || (dz == -r);
            for (int dy = -r; dy <= r; dy++) {
                int yy = cy + dy;
                if ((unsigned)yy >= G) continue;
                int rowb = (z * G + yy) * G;
                if (zedge || dy == r || dy == -r) {
                    // full row of the ring
                    int lo = max(cx - r, 0), hi = min(cx + r, G - 1);
                    best = scan_range(st, cs, pp, rowb + lo, rowb + hi, q0, q1, q2, best);
                } else {
                    // interior row: only the two edge cells dx = +-r
                    int cl = cx - r;
                    if (cl >= 0)
                        best = scan_range(st, cs, pp, rowb + cl, rowb + cl, q0, q1, q2, best);
                    int ch = cx + r;
                    if (ch < G)
                        best = scan_range(st, cs, pp, rowb + ch, rowb + ch, q0, q1, q2, best);
                }
            }
        }
        // Points in unscanned rings (>= r+1) are at distance >= r*h.
        float bnd = (float)r * H;
        if (best <= bnd * bnd) break;
    }
    g_res[tid] = fmaxf(best, 0.0f);
}

// ---------------- 6a. 64-CTA deterministic partial sums ----------------
__global__ void sumA_kernel() {
    __shared__ float red[256];
    const float4* gp = (const float4*)g_res;
    float4 v = gp[blockIdx.x * 256 + threadIdx.x];
    float ss = (v.x + v.y) + (v.z + v.w);
    red[threadIdx.x] = ss;
    __syncthreads();
    for (int k = 128; k > 0; k >>= 1) {
        if (threadIdx.x < k) red[threadIdx.x] += red[threadIdx.x + k];
        __syncthreads();
    }
    if (threadIdx.x == 0) g_part[blockIdx.x] = red[0];
}

// ---------------- 6b. combine partials + scale ----------------
__global__ void sumB_kernel(float* __restrict__ out) {
    __shared__ float red[SUMA_CTAS];
    red[threadIdx.x] = g_part[threadIdx.x];
    __syncthreads();
    for (int k = SUMA_CTAS / 2; k > 0; k >>= 1) {
        if (threadIdx.x < k) red[threadIdx.x] += red[threadIdx.x + k];
        __syncthreads();
    }
    if (threadIdx.x == 0)
        out[0] = red[0] * (1.0f / (float)(BATCH * NPTS));
}

extern "C" void kernel_launch(void* const* d_in, const int* in_sizes, int n_in,
                              void* d_out, int out_size) {
    const float* x = (const float*)d_in[0];
    const float* y = (const float*)d_in[1];
    float* out = (float*)d_out;
    (void)in_sizes; (void)n_in; (void)out_size;

    zero_cnt_kernel<<<NGRIDS * NC / 4 / 256, 256>>>();
    count_kernel<<<TOTQ / 256, 256>>>(x, y);
    scanA_kernel<<<SCANA_CTAS, 1024>>>();
    scanB_kernel<<<1, SCANA_CTAS>>>();
    scanC_kernel<<<NGRIDS * NC / 256, 256>>>();
    scatter_kernel<<<TOTQ / 256, 256>>>(x, y);
    query_kernel<<<TOTQ / 256, 256>>>(x, y);
    sumA_kernel<<<SUMA_CTAS, 256>>>();
    sumB_kernel<<<1, SUMA_CTAS>>>(out);
}

// round 9
// speedup vs baseline: 8.1461x; 8.1461x over previous
#include <cuda_runtime.h>
#include <cstdint>

// Problem shape (fixed by the reference): B=4, N=M=8192, D=3, fp32.
// Exact nearest-neighbor via uniform grid (G=16) + pruned cube expansion.
#define BATCH   4
#define NPTS    8192
#define G       16
#define NC      (G * G * G)            // 4096 cells per grid
#define NGRIDS  (2 * BATCH)            // 8: [0..3]=y content per batch, [4..7]=x content
#define TOTQ    (2 * BATCH * NPTS)     // 65536 queries
#define GS      1.6f                   // G / 10
#define H       0.625f                 // 10 / G (exact in fp32)
#define LOV     (-5.0f)
#define EPS     1e-3f
#define SUMA_CTAS 64

// Static scratch (zero-initialized at load; g_cnt re-zeroed by sumA each replay).
__device__ int    g_cnt[NGRIDS * NC];
__device__ int    g_start[NGRIDS * NC];
__device__ int    g_end[NGRIDS * NC];
__device__ int    g_cursor[NGRIDS * NC];
__device__ float4 g_pts[NGRIDS * NPTS];
__device__ float  g_res[TOTQ];
__device__ float  g_part[SUMA_CTAS];

__device__ __forceinline__ int cellco(float v) {
    int c = (int)((v - LOV) * GS);     // CUDA f2i saturates, then clamp
    return min(max(c, 0), G - 1);
}

// ---------------- 1. count points per cell ----------------
__global__ void count_kernel(const float* __restrict__ x, const float* __restrict__ y) {
    int tid = blockIdx.x * blockDim.x + threadIdx.x;   // 65536
    int i = tid & (NPTS - 1);
    int b = (tid >> 13) & 3;
    int s = tid >> 15;                                  // 0: content y, 1: content x
    const float* src = s ? x : y;
    const float* p = src + ((size_t)b * NPTS + i) * 3;
    int cell = (cellco(p[2]) * G + cellco(p[1])) * G + cellco(p[0]);
    atomicAdd(&g_cnt[(s * BATCH + b) * NC + cell], 1);
}

// ---------------- 2. per-grid scan: starts, ends, cursors (one block per grid) ----------------
__global__ void scan_kernel() {
    __shared__ int sm[1024];
    int t = threadIdx.x;
    int base = blockIdx.x * NC + t * 4;
    int c0 = g_cnt[base], c1 = g_cnt[base + 1], c2 = g_cnt[base + 2], c3 = g_cnt[base + 3];
    int tot = c0 + c1 + c2 + c3;
    sm[t] = tot;
    __syncthreads();
    for (int off = 1; off < 1024; off <<= 1) {
        int v = (t >= off) ? sm[t - off] : 0;
        __syncthreads();
        sm[t] += v;
        __syncthreads();
    }
    int e = sm[t] - tot;
    int s0 = e, s1 = e + c0, s2 = s1 + c1, s3 = s2 + c2;
    g_start[base] = s0;  g_end[base] = s1;      g_cursor[base] = s0;
    g_start[base+1] = s1; g_end[base+1] = s2;   g_cursor[base+1] = s1;
    g_start[base+2] = s2; g_end[base+2] = s3;   g_cursor[base+2] = s2;
    g_start[base+3] = s3; g_end[base+3] = s3 + c3; g_cursor[base+3] = s3;
}

// ---------------- 3. scatter points into CSR order ----------------
__global__ void scatter_kernel(const float* __restrict__ x, const float* __restrict__ y) {
    int tid = blockIdx.x * blockDim.x + threadIdx.x;
    int i = tid & (NPTS - 1);
    int b = (tid >> 13) & 3;
    int s = tid >> 15;
    const float* src = s ? x : y;
    const float* p = src + ((size_t)b * NPTS + i) * 3;
    float p0 = p[0], p1 = p[1], p2 = p[2];
    int cell = (cellco(p2) * G + cellco(p1)) * G + cellco(p0);
    int g = s * BATCH + b;
    int pos = atomicAdd(&g_cursor[g * NC + cell], 1);
    g_pts[g * NPTS + pos] = make_float4(p0, p1, p2, 0.0f);
}

// ---------------- 4. query: exact NN, cube expansion with box-distance pruning ----------------
__global__ void query_kernel(const float* __restrict__ x, const float* __restrict__ y) {
    int tid = blockIdx.x * blockDim.x + threadIdx.x;   // 65536; block = one (s,b) group
    int i = tid & (NPTS - 1);
    int b = (tid >> 13) & 3;
    int s = tid >> 15;                   // 0: x queries -> y grid (g=b); 1: y queries -> x grid
    const float* src = s ? y : x;
    const float* q = src + ((size_t)b * NPTS + i) * 3;
    float q0 = q[0], q1 = q[1], q2 = q[2];
    int g = s ? (BATCH + b) : b;

    const int*    st = g_start + g * NC;
    const int*    en = g_end   + g * NC;
    const float4* pp = g_pts   + g * NPTS;

    int cx = cellco(q0), cy = cellco(q1), cz = cellco(q2);
    float best = 3.0e38f;

    // center cell first (establishes a tight best for pruning)
    {
        int c = (cz * G + cy) * G + cx;
        int j0 = st[c], j1 = en[c];
        for (int j = j0; j < j1; j++) {
            float4 p = pp[j];
            float d0 = q0 - p.x, d1 = q1 - p.y, d2 = q2 - p.z;
            best = fminf(best, fmaf(d0, d0, fmaf(d1, d1, d2 * d2)));
        }
    }

    for (int r = 1; ; r++) {
        int zl = max(cz - r, 0), zh = min(cz + r, G - 1);
        int yl = max(cy - r, 0), yh = min(cy + r, G - 1);
        for (int z = zl; z <= zh; z++) {
            // exact distance from qz to cell-z slab (clamped boundary cells are conservative)
            float dzd = 0.0f;
            if (z < cz)      dzd = q2 - (LOV + (float)(z + 1) * H);
            else if (z > cz) dzd = (LOV + (float)z * H) - q2;
            dzd = fmaxf(dzd - EPS, 0.0f);
            float dz2 = dzd * dzd;
            if (dz2 >= best) continue;
            for (int yy = yl; yy <= yh; yy++) {
                float dyd = 0.0f;
                if (yy < cy)      dyd = q1 - (LOV + (float)(yy + 1) * H);
                else if (yy > cy) dyd = (LOV + (float)yy * H) - q1;
                dyd = fmaxf(dyd - EPS, 0.0f);
                float rb = fmaf(dyd, dyd, dz2);
                if (rb >= best) continue;
                float rad = sqrtf(best - rb);
                int xl = max(cellco(q0 - rad), max(cx - r, 0));
                int xh = min(cellco(q0 + rad), min(cx + r, G - 1));
                if (xl > xh) continue;
                int rowb = (z * G + yy) * G;
                int j0 = st[rowb + xl], j1 = en[rowb + xh];
                for (int j = j0; j < j1; j++) {
                    float4 p = pp[j];
                    float d0 = q0 - p.x, d1 = q1 - p.y, d2 = q2 - p.z;
                    best = fminf(best, fmaf(d0, d0, fmaf(d1, d1, d2 * d2)));
                }
            }
        }
        // unscanned cells (Chebyshev >= r+1) hold points at distance >= r*H (minus fp slack)
        float bnd = (float)r * H - 0.01f;
        if (best <= bnd * bnd || r >= G - 1) break;
    }
    g_res[tid] = fmaxf(best, 0.0f);
}

// ---------------- 5a. 64-CTA deterministic partial sums (+ re-zero counts) ----------------
__global__ void sumA_kernel() {
    __shared__ float red[256];
    const float4* gp = (const float4*)g_res;
    float4 v = gp[blockIdx.x * 256 + threadIdx.x];
    float ss = (v.x + v.y) + (v.z + v.w);
    // fused: reset cell counts for the next replay (32768 ints = 16384 int2)
    ((int2*)g_cnt)[blockIdx.x * 256 + threadIdx.x] = make_int2(0, 0);
    red[threadIdx.x] = ss;
    __syncthreads();
    for (int k = 128; k > 0; k >>= 1) {
        if (threadIdx.x < k) red[threadIdx.x] += red[threadIdx.x + k];
        __syncthreads();
    }
    if (threadIdx.x == 0) g_part[blockIdx.x] = red[0];
}

// ---------------- 5b. combine partials + scale ----------------
__global__ void sumB_kernel(float* __restrict__ out) {
    __shared__ float red[SUMA_CTAS];
    red[threadIdx.x] = g_part[threadIdx.x];
    __syncthreads();
    for (int k = SUMA_CTAS / 2; k > 0; k >>= 1) {
        if (threadIdx.x < k) red[threadIdx.x] += red[threadIdx.x + k];
        __syncthreads();
    }
    if (threadIdx.x == 0)
        out[0] = red[0] * (1.0f / (float)(BATCH * NPTS));
}

extern "C" void kernel_launch(void* const* d_in, const int* in_sizes, int n_in,
                              void* d_out, int out_size) {
    const float* x = (const float*)d_in[0];
    const float* y = (const float*)d_in[1];
    float* out = (float*)d_out;
    (void)in_sizes; (void)n_in; (void)out_size;

    count_kernel<<<TOTQ / 256, 256>>>(x, y);
    scan_kernel<<<NGRIDS, 1024>>>();
    scatter_kernel<<<TOTQ / 256, 256>>>(x, y);
    query_kernel<<<TOTQ / 256, 256>>>(x, y);
    sumA_kernel<<<SUMA_CTAS, 256>>>();
    sumB_kernel<<<1, SUMA_CTAS>>>(out);
}